// round 8
// baseline (speedup 1.0000x reference)
#include <cuda_runtime.h>
#include <cuda_bf16.h>
#include <cstdint>
#include <cstddef>

#define NN 100000
#define EE 1600000
#define C  128
#define NB 98                 // scan blocks: ceil(100000/1024)

// ---- scratch (device globals: allocation-free) ----
__device__ float g_h1 [(size_t)NN * C];
__device__ float g_h2 [(size_t)NN * C];
__device__ int   g_cnt[NN];
__device__ int   g_rowptr[NN + 1];
__device__ int   g_cursor[NN];
__device__ int   g_part[NB];
__device__ int   g_srcs[EE];
__device__ __nv_bfloat16 g_whi[6 * 16384];
__device__ __nv_bfloat16 g_wlo[6 * 16384];

// ---------------------------------------------------------------------------
// helpers
// ---------------------------------------------------------------------------
__device__ __forceinline__ uint32_t smem_u32(const void* p) {
    uint32_t a;
    asm("{ .reg .u64 t; cvta.to.shared.u64 t, %1; cvt.u32.u64 %0, t; }"
        : "=r"(a) : "l"(p));
    return a;
}
__device__ __forceinline__ void cp16(uint32_t saddr, const void* g) {
    asm volatile("cp.async.cg.shared.global [%0], [%1], 16;"
                 :: "r"(saddr), "l"(g) : "memory");
}
__device__ __forceinline__ void ldsm4(uint32_t addr, uint32_t* r) {
    asm volatile("ldmatrix.sync.aligned.m8n8.x4.shared.b16 {%0,%1,%2,%3}, [%4];"
                 : "=r"(r[0]), "=r"(r[1]), "=r"(r[2]), "=r"(r[3]) : "r"(addr));
}
__device__ __forceinline__ void mma16816(float* c, const uint32_t* a, const uint32_t* b) {
    asm volatile(
        "mma.sync.aligned.m16n8k16.row.col.f32.bf16.bf16.f32 "
        "{%0,%1,%2,%3}, {%4,%5,%6,%7}, {%8,%9}, {%0,%1,%2,%3};"
        : "+f"(c[0]), "+f"(c[1]), "+f"(c[2]), "+f"(c[3])
        : "r"(a[0]), "r"(a[1]), "r"(a[2]), "r"(a[3]), "r"(b[0]), "r"(b[1]));
}
__device__ __forceinline__ uint32_t packbf2(float f0, float f1) {
    uint32_t r;
    asm("cvt.rn.bf16x2.f32 %0, %1, %2;" : "=r"(r) : "f"(f1), "f"(f0));
    return r;
}
__device__ __forceinline__ int warp_iscan(int v, int lane) {
#pragma unroll
    for (int d = 1; d < 32; d <<= 1) {
        int n = __shfl_up_sync(0xFFFFFFFFu, v, d);
        if (lane >= d) v += n;
    }
    return v;
}

// ---------------------------------------------------------------------------
// zero fill
// ---------------------------------------------------------------------------
__global__ void zero_i(int* __restrict__ p, int n) {
    int i = blockIdx.x * blockDim.x + threadIdx.x;
    if (i < n) p[i] = 0;
}

// ---------------------------------------------------------------------------
// one-shot weight split
// ---------------------------------------------------------------------------
__global__ void split_weights(const float* __restrict__ Wl1, const float* __restrict__ Wr1,
                              const float* __restrict__ Wl2, const float* __restrict__ Wr2,
                              const float* __restrict__ Wlin,
                              __nv_bfloat16* __restrict__ whi,
                              __nv_bfloat16* __restrict__ wlo)
{
    int i = blockIdx.x * blockDim.x + threadIdx.x;
    if (i >= 6 * 16384) return;
    int s = i >> 14, r = (i >> 7) & 127, k = i & 127;
    float v;
    switch (s) {
        case 0:  v = __ldg(Wl1 + r * 128 + k); break;
        case 1:  v = __ldg(Wr1 + r * 128 + k); break;
        case 2:  v = __ldg(Wl2 + r * 128 + k); break;
        case 3:  v = __ldg(Wr2 + r * 128 + k); break;
        case 4:  v = __ldg(Wlin + r * 256 + k); break;
        default: v = __ldg(Wlin + r * 256 + 128 + k); break;
    }
    __nv_bfloat16 h = __float2bfloat16(v);
    whi[i] = h;
    wlo[i] = __float2bfloat16(v - __bfloat162float(h));
}

// ---------------------------------------------------------------------------
// CSR build: histogram -> 3-phase scan -> bucket scatter
// ---------------------------------------------------------------------------
__global__ void hist_kernel(const int* __restrict__ dst, int* __restrict__ cnt) {
    int e = blockIdx.x * blockDim.x + threadIdx.x;
    if (e < EE) atomicAdd(cnt + __ldg(dst + e), 1);
}

__global__ __launch_bounds__(1024) void scan_blk(
    const int* __restrict__ cnt, int* __restrict__ rowptr, int* __restrict__ part)
{
    __shared__ int ws[32];
    const int t = threadIdx.x, lane = t & 31, w = t >> 5;
    const int i = blockIdx.x * 1024 + t;
    const int v = (i < NN) ? __ldg(cnt + i) : 0;

    int x = warp_iscan(v, lane);
    if (lane == 31) ws[w] = x;
    __syncthreads();
    if (w == 0) ws[lane] = warp_iscan(ws[lane], lane);
    __syncthreads();

    const int incl = x + (w ? ws[w - 1] : 0);
    if (i < NN) rowptr[i] = incl - v;
    if (t == 1023) part[blockIdx.x] = incl;
}

__global__ __launch_bounds__(128) void scan_part(int* __restrict__ part) {
    __shared__ int ws[4];
    const int t = threadIdx.x, lane = t & 31, w = t >> 5;
    const int v = (t < NB) ? part[t] : 0;
    int x = warp_iscan(v, lane);
    if (lane == 31) ws[w] = x;
    __syncthreads();
    if (t == 0) {
        int run = 0;
        for (int j = 0; j < 4; j++) { int s = ws[j]; ws[j] = run; run += s; }
    }
    __syncthreads();
    if (t < NB) part[t] = x - v + ws[w];
}

__global__ __launch_bounds__(1024) void scan_add(
    const int* __restrict__ part, int* __restrict__ rowptr, int* __restrict__ cursor)
{
    const int i = blockIdx.x * 1024 + threadIdx.x;
    if (i < NN) {
        int r = rowptr[i] + part[blockIdx.x];
        rowptr[i] = r;
        cursor[i] = r;
    }
    if (i == 0) rowptr[NN] = EE;
}

__global__ void scatter_csr(const int* __restrict__ src, const int* __restrict__ dst,
                            int* __restrict__ cursor, int* __restrict__ srcs)
{
    int e = blockIdx.x * blockDim.x + threadIdx.x;
    if (e >= EE) return;
    int d = __ldg(dst + e);
    int pos = atomicAdd(cursor + d, 1);
    srcs[pos] = __ldg(src + e);
}

// ---------------------------------------------------------------------------
// HMMA fused dual-matmul layer with in-kernel CSR mean aggregation.
//   out[n][o] = relu( mean_{s in N(n)} feat1[s] · W{s0}[o] + A2[n] · W{s1}[o] + bias[o] )
// When rowptr == nullptr, pass 0 uses plain row loads of feat1 (head layer).
//
// 256 thr, tile 128x128. Warp tile 32x64, m16n8k16 bf16 via ldmatrix.x4.
// Split-bf16 emulated fp32 (3 MMAs). SMEM 73728 B -> 2 CTAs/SM.
// ---------------------------------------------------------------------------
#define PITCH  72
#define SLAB_B (128 * PITCH * 2)
#define AH_OFF 0
#define AL_OFF SLAB_B
#define WH_OFF (2 * SLAB_B)
#define WL_OFF (3 * SLAB_B)
#define SMEM_BYTES (4 * SLAB_B)         // 73728

__global__ __launch_bounds__(256, 2) void hmma_layer(
    const float* __restrict__ feat1, const float* __restrict__ A2,
    const int* __restrict__ rowptr, const int* __restrict__ srcs,
    const __nv_bfloat16* __restrict__ whi, const __nv_bfloat16* __restrict__ wlo,
    int s0, int s1,
    const float* __restrict__ bias,
    float* __restrict__ out, int nrows)
{
    extern __shared__ char sm[];
    const uint32_t smb = smem_u32(sm);
    const int t = threadIdx.x, wid = t >> 5, lane = t & 31;
    const int nb = blockIdx.x * 128;

    const int mBase = (wid & 3) * 32;
    const int nBase = (wid >> 2) * 64;

    const int arow = (lane & 7) + ((lane >> 3) & 1) * 8;
    const int acol = (lane >> 4) * 8;
    const int brow = (lane & 7) + (lane >> 4) * 8;
    const int bcol = ((lane >> 3) & 1) * 8;
    const uint32_t aoff0 = ((mBase + arow) * PITCH + acol) * 2;
    const uint32_t aoff1 = aoff0 + 16 * PITCH * 2;
    const uint32_t boff  = ((nBase + brow) * PITCH + bcol) * 2;

    float acc[2][8][4];
#pragma unroll
    for (int mt = 0; mt < 2; mt++)
#pragma unroll
        for (int nt = 0; nt < 8; nt++)
#pragma unroll
            for (int j = 0; j < 4; j++) acc[mt][nt][j] = 0.f;

#pragma unroll 1
    for (int pass = 0; pass < 2; pass++) {
        const __nv_bfloat16* Wh = whi + (size_t)(pass ? s1 : s0) * 16384;
        const __nv_bfloat16* Wl = wlo + (size_t)(pass ? s1 : s0) * 16384;
        const bool csr = (pass == 0) && (rowptr != nullptr);

#pragma unroll 1
        for (int chunk = 0; chunk < 2; chunk++) {
            const int k0 = chunk * 64;

            // -- W tile copy via cp.async (overlaps with A staging below) --
            for (int i = t; i < 2048; i += 256) {
                const int slab = i >> 10;
                const int r    = (i >> 3) & 127;
                const int seg  = i & 7;
                const uint32_t sa = smb + (slab ? WL_OFF : WH_OFF)
                                  + r * (PITCH * 2) + seg * 16;
                const __nv_bfloat16* g = (slab ? Wl : Wh) + (size_t)r * 128 + k0 + seg * 8;
                cp16(sa, g);
            }
            asm volatile("cp.async.commit_group;" ::: "memory");

            if (csr) {
                // -- A tile: CSR gather + mean, split to hi/lo bf16 --
                // one warp per row (8 warps x 16 rows); lane owns cols (2l, 2l+1)
                const float* fbase = feat1 + k0 + 2 * lane;
#pragma unroll 1
                for (int r16 = 0; r16 < 16; r16++) {
                    const int r  = wid * 16 + r16;
                    const int gn = nb + r;
                    float ax = 0.f, ay = 0.f;
                    if (gn < nrows) {
                        const int beg = __ldg(rowptr + gn);
                        const int end = __ldg(rowptr + gn + 1);
                        int e = beg;
                        for (; e + 4 <= end; e += 4) {
                            int i0 = __ldg(srcs + e);
                            int i1 = __ldg(srcs + e + 1);
                            int i2 = __ldg(srcs + e + 2);
                            int i3 = __ldg(srcs + e + 3);
                            float2 v0 = __ldg((const float2*)(fbase + (size_t)i0 * C));
                            float2 v1 = __ldg((const float2*)(fbase + (size_t)i1 * C));
                            float2 v2 = __ldg((const float2*)(fbase + (size_t)i2 * C));
                            float2 v3 = __ldg((const float2*)(fbase + (size_t)i3 * C));
                            ax += (v0.x + v1.x) + (v2.x + v3.x);
                            ay += (v0.y + v1.y) + (v2.y + v3.y);
                        }
                        for (; e < end; e++) {
                            int i0 = __ldg(srcs + e);
                            float2 v0 = __ldg((const float2*)(fbase + (size_t)i0 * C));
                            ax += v0.x; ay += v0.y;
                        }
                        const int deg = end - beg;
                        const float inv = 1.f / (float)(deg > 1 ? deg : 1);
                        ax *= inv; ay *= inv;
                    }
                    uint32_t h = packbf2(ax, ay);
                    float lx = ax - __uint_as_float(h << 16);
                    float ly = ay - __uint_as_float(h & 0xFFFF0000u);
                    uint32_t l = packbf2(lx, ly);
                    const uint32_t so = r * (PITCH * 2) + lane * 4;
                    *(uint32_t*)(sm + AH_OFF + so) = h;
                    *(uint32_t*)(sm + AL_OFF + so) = l;
                }
            } else {
                // -- A tile: plain fp32 rows -> split --
                const float* A = pass ? A2 : feat1;
                for (int i = t; i < 2048; i += 256) {
                    const int r  = i >> 4;
                    const int f4 = i & 15;
                    const int gn = nb + r;
                    float4 v = make_float4(0.f, 0.f, 0.f, 0.f);
                    if (gn < nrows)
                        v = __ldg((const float4*)(A + (size_t)gn * C + k0 + f4 * 4));
                    uint32_t h0 = packbf2(v.x, v.y);
                    uint32_t h1 = packbf2(v.z, v.w);
                    float l00 = v.x - __uint_as_float(h0 << 16);
                    float l01 = v.y - __uint_as_float(h0 & 0xFFFF0000u);
                    float l10 = v.z - __uint_as_float(h1 << 16);
                    float l11 = v.w - __uint_as_float(h1 & 0xFFFF0000u);
                    uint32_t l0 = packbf2(l00, l01);
                    uint32_t l1 = packbf2(l10, l11);
                    const size_t so = (size_t)r * (PITCH * 2) + f4 * 8;
                    *(uint2*)(sm + AH_OFF + so) = make_uint2(h0, h1);
                    *(uint2*)(sm + AL_OFF + so) = make_uint2(l0, l1);
                }
            }
            asm volatile("cp.async.wait_group 0;" ::: "memory");
            __syncthreads();

#pragma unroll
            for (int ks = 0; ks < 4; ks++) {
                uint32_t ah0[4], ah1[4], al0[4], al1[4];
                ldsm4(smb + AH_OFF + aoff0 + ks * 32, ah0);
                ldsm4(smb + AH_OFF + aoff1 + ks * 32, ah1);
                ldsm4(smb + AL_OFF + aoff0 + ks * 32, al0);
                ldsm4(smb + AL_OFF + aoff1 + ks * 32, al1);
#pragma unroll
                for (int p = 0; p < 4; p++) {
                    uint32_t bh[4], bl[4];
                    const uint32_t bo = boff + p * (16 * PITCH * 2) + ks * 32;
                    ldsm4(smb + WH_OFF + bo, bh);
                    ldsm4(smb + WL_OFF + bo, bl);
                    mma16816(acc[0][2 * p],     ah0, bh);
                    mma16816(acc[1][2 * p],     ah1, bh);
                    mma16816(acc[0][2 * p],     al0, bh);
                    mma16816(acc[1][2 * p],     al1, bh);
                    mma16816(acc[0][2 * p],     ah0, bl);
                    mma16816(acc[1][2 * p],     ah1, bl);
                    mma16816(acc[0][2 * p + 1], ah0, bh + 2);
                    mma16816(acc[1][2 * p + 1], ah1, bh + 2);
                    mma16816(acc[0][2 * p + 1], al0, bh + 2);
                    mma16816(acc[1][2 * p + 1], al1, bh + 2);
                    mma16816(acc[0][2 * p + 1], ah0, bl + 2);
                    mma16816(acc[1][2 * p + 1], ah1, bl + 2);
                }
            }
            __syncthreads();
        }
    }

    // -- epilogue: bias + relu, registers -> gmem --
    const int qrow = lane >> 2;
    const int qk   = (lane & 3) * 2;
#pragma unroll
    for (int nt = 0; nt < 8; nt++) {
        const int cl = nBase + nt * 8 + qk;
        const float2 b = __ldg((const float2*)(bias + cl));
#pragma unroll
        for (int mt = 0; mt < 2; mt++) {
            const int r0 = nb + mBase + mt * 16 + qrow;
            if (r0 < nrows) {
                float2 o;
                o.x = fmaxf(acc[mt][nt][0] + b.x, 0.f);
                o.y = fmaxf(acc[mt][nt][1] + b.y, 0.f);
                *(float2*)(out + (size_t)r0 * C + cl) = o;
            }
            const int r1 = r0 + 8;
            if (r1 < nrows) {
                float2 o;
                o.x = fmaxf(acc[mt][nt][2] + b.x, 0.f);
                o.y = fmaxf(acc[mt][nt][3] + b.y, 0.f);
                *(float2*)(out + (size_t)r1 * C + cl) = o;
            }
        }
    }
}

// ---------------------------------------------------------------------------
// launch
// ---------------------------------------------------------------------------
extern "C" void kernel_launch(void* const* d_in, const int* in_sizes, int n_in,
                              void* d_out, int out_size)
{
    const float* x    = (const float*)d_in[0];
    const int*   ei   = (const int*)  d_in[1];
    const float* Wl1  = (const float*)d_in[2];
    const float* Wr1  = (const float*)d_in[3];
    const float* b1   = (const float*)d_in[4];
    const float* Wl2  = (const float*)d_in[5];
    const float* Wr2  = (const float*)d_in[6];
    const float* b2   = (const float*)d_in[7];
    const float* Wlin = (const float*)d_in[8];
    const float* blin = (const float*)d_in[9];
    float*       out  = (float*)d_out;

    const int* src = ei;
    const int* dst = ei + EE;

    void *h1_v, *h2_v, *cnt_v, *rp_v, *cur_v, *part_v, *srcs_v, *whi_v, *wlo_v;
    cudaGetSymbolAddress(&h1_v,  g_h1);
    cudaGetSymbolAddress(&h2_v,  g_h2);
    cudaGetSymbolAddress(&cnt_v, g_cnt);
    cudaGetSymbolAddress(&rp_v,  g_rowptr);
    cudaGetSymbolAddress(&cur_v, g_cursor);
    cudaGetSymbolAddress(&part_v, g_part);
    cudaGetSymbolAddress(&srcs_v, g_srcs);
    cudaGetSymbolAddress(&whi_v, g_whi);
    cudaGetSymbolAddress(&wlo_v, g_wlo);
    float* h1  = (float*)h1_v;
    float* h2  = (float*)h2_v;
    int*   cnt = (int*)cnt_v;
    int*   rowptr = (int*)rp_v;
    int*   cursor = (int*)cur_v;
    int*   part   = (int*)part_v;
    int*   srcs   = (int*)srcs_v;
    __nv_bfloat16* whi = (__nv_bfloat16*)whi_v;
    __nv_bfloat16* wlo = (__nv_bfloat16*)wlo_v;

    cudaFuncSetAttribute(hmma_layer,
                         cudaFuncAttributeMaxDynamicSharedMemorySize, SMEM_BYTES);

    const int eblk = (EE + 255) / 256;          // 6250
    const int gblk = (NN + 127) / 128;          // 782
    const int wblk = (6 * 16384 + 255) / 256;

    // ---- prep: weight split + CSR build ----
    split_weights<<<wblk, 256>>>(Wl1, Wr1, Wl2, Wr2, Wlin, whi, wlo);
    zero_i<<<(NN + 255) / 256, 256>>>(cnt, NN);
    hist_kernel<<<eblk, 256>>>(dst, cnt);
    scan_blk<<<NB, 1024>>>(cnt, rowptr, part);
    scan_part<<<1, 128>>>(part);
    scan_add<<<NB, 1024>>>(part, rowptr, cursor);
    scatter_csr<<<eblk, 256>>>(src, dst, cursor, srcs);

    // ---- conv1: gather(x) · Wl1 + x · Wr1 ----
    hmma_layer<<<gblk, 256, SMEM_BYTES>>>(x, x, rowptr, srcs, whi, wlo, 0, 1, b1, h1, NN);

    // ---- conv2: gather(h1) · Wl2 + h1 · Wr2 ----
    hmma_layer<<<gblk, 256, SMEM_BYTES>>>(h1, h1, rowptr, srcs, whi, wlo, 2, 3, b2, h2, NN);

    // ---- JK-cat + linear head: h1 · Wlin[:, :128] + h2 · Wlin[:, 128:] ----
    hmma_layer<<<gblk, 256, SMEM_BYTES>>>(h1, h2, nullptr, nullptr, whi, wlo, 4, 5,
                                          blin, out, NN);
}

// round 9
// speedup vs baseline: 1.8143x; 1.8143x over previous
#include <cuda_runtime.h>
#include <cuda_bf16.h>
#include <cuda_fp16.h>
#include <cstdint>
#include <cstddef>

#define NN 100000
#define EE 1600000
#define C  128
#define NB 98                 // scan blocks: ceil(100000/1024)

// ---- scratch (device globals: allocation-free) ----
__device__ float  g_agg[(size_t)NN * C];
__device__ float  g_h1 [(size_t)NN * C];
__device__ float  g_h2 [(size_t)NN * C];
__device__ __half g_xh [(size_t)NN * C];   // fp16 gather table for x
__device__ __half g_h1h[(size_t)NN * C];   // fp16 gather table for h1
__device__ int    g_cnt[NN];
__device__ int    g_rowptr[NN + 1];
__device__ int    g_cursor[NN];
__device__ int    g_part[NB];
__device__ int    g_srcs[EE];
__device__ __nv_bfloat16 g_whi[6 * 16384];
__device__ __nv_bfloat16 g_wlo[6 * 16384];

// ---------------------------------------------------------------------------
// helpers
// ---------------------------------------------------------------------------
__device__ __forceinline__ uint32_t smem_u32(const void* p) {
    uint32_t a;
    asm("{ .reg .u64 t; cvta.to.shared.u64 t, %1; cvt.u32.u64 %0, t; }"
        : "=r"(a) : "l"(p));
    return a;
}
__device__ __forceinline__ void cp16(uint32_t saddr, const void* g) {
    asm volatile("cp.async.cg.shared.global [%0], [%1], 16;"
                 :: "r"(saddr), "l"(g) : "memory");
}
__device__ __forceinline__ void ldsm4(uint32_t addr, uint32_t* r) {
    asm volatile("ldmatrix.sync.aligned.m8n8.x4.shared.b16 {%0,%1,%2,%3}, [%4];"
                 : "=r"(r[0]), "=r"(r[1]), "=r"(r[2]), "=r"(r[3]) : "r"(addr));
}
__device__ __forceinline__ void mma16816(float* c, const uint32_t* a, const uint32_t* b) {
    asm volatile(
        "mma.sync.aligned.m16n8k16.row.col.f32.bf16.bf16.f32 "
        "{%0,%1,%2,%3}, {%4,%5,%6,%7}, {%8,%9}, {%0,%1,%2,%3};"
        : "+f"(c[0]), "+f"(c[1]), "+f"(c[2]), "+f"(c[3])
        : "r"(a[0]), "r"(a[1]), "r"(a[2]), "r"(a[3]), "r"(b[0]), "r"(b[1]));
}
__device__ __forceinline__ uint32_t packbf2(float f0, float f1) {
    uint32_t r;
    asm("cvt.rn.bf16x2.f32 %0, %1, %2;" : "=r"(r) : "f"(f1), "f"(f0));
    return r;
}
__device__ __forceinline__ int warp_iscan(int v, int lane) {
#pragma unroll
    for (int d = 1; d < 32; d <<= 1) {
        int n = __shfl_up_sync(0xFFFFFFFFu, v, d);
        if (lane >= d) v += n;
    }
    return v;
}

// ---------------------------------------------------------------------------
// zero fill / fp32 -> fp16 table
// ---------------------------------------------------------------------------
__global__ void zero_i(int* __restrict__ p, int n) {
    int i = blockIdx.x * blockDim.x + threadIdx.x;
    if (i < n) p[i] = 0;
}

__global__ void to_half(const float* __restrict__ src, __half* __restrict__ dst, int n4) {
    int i = blockIdx.x * blockDim.x + threadIdx.x;
    if (i >= n4) return;
    float4 v = __ldg((const float4*)src + i);
    __half2 h0 = __floats2half2_rn(v.x, v.y);
    __half2 h1 = __floats2half2_rn(v.z, v.w);
    *(uint2*)(dst + (size_t)i * 4) = make_uint2(*(uint32_t*)&h0, *(uint32_t*)&h1);
}

// ---------------------------------------------------------------------------
// one-shot weight split
// ---------------------------------------------------------------------------
__global__ void split_weights(const float* __restrict__ Wl1, const float* __restrict__ Wr1,
                              const float* __restrict__ Wl2, const float* __restrict__ Wr2,
                              const float* __restrict__ Wlin,
                              __nv_bfloat16* __restrict__ whi,
                              __nv_bfloat16* __restrict__ wlo)
{
    int i = blockIdx.x * blockDim.x + threadIdx.x;
    if (i >= 6 * 16384) return;
    int s = i >> 14, r = (i >> 7) & 127, k = i & 127;
    float v;
    switch (s) {
        case 0:  v = __ldg(Wl1 + r * 128 + k); break;
        case 1:  v = __ldg(Wr1 + r * 128 + k); break;
        case 2:  v = __ldg(Wl2 + r * 128 + k); break;
        case 3:  v = __ldg(Wr2 + r * 128 + k); break;
        case 4:  v = __ldg(Wlin + r * 256 + k); break;
        default: v = __ldg(Wlin + r * 256 + 128 + k); break;
    }
    __nv_bfloat16 h = __float2bfloat16(v);
    whi[i] = h;
    wlo[i] = __float2bfloat16(v - __bfloat162float(h));
}

// ---------------------------------------------------------------------------
// CSR build: histogram -> 3-phase scan -> bucket scatter
// ---------------------------------------------------------------------------
__global__ void hist_kernel(const int* __restrict__ dst, int* __restrict__ cnt) {
    int e = blockIdx.x * blockDim.x + threadIdx.x;
    if (e < EE) atomicAdd(cnt + __ldg(dst + e), 1);
}

__global__ __launch_bounds__(1024) void scan_blk(
    const int* __restrict__ cnt, int* __restrict__ rowptr, int* __restrict__ part)
{
    __shared__ int ws[32];
    const int t = threadIdx.x, lane = t & 31, w = t >> 5;
    const int i = blockIdx.x * 1024 + t;
    const int v = (i < NN) ? __ldg(cnt + i) : 0;

    int x = warp_iscan(v, lane);
    if (lane == 31) ws[w] = x;
    __syncthreads();
    if (w == 0) ws[lane] = warp_iscan(ws[lane], lane);
    __syncthreads();

    const int incl = x + (w ? ws[w - 1] : 0);
    if (i < NN) rowptr[i] = incl - v;
    if (t == 1023) part[blockIdx.x] = incl;
}

__global__ __launch_bounds__(128) void scan_part(int* __restrict__ part) {
    __shared__ int ws[4];
    const int t = threadIdx.x, lane = t & 31, w = t >> 5;
    const int v = (t < NB) ? part[t] : 0;
    int x = warp_iscan(v, lane);
    if (lane == 31) ws[w] = x;
    __syncthreads();
    if (t == 0) {
        int run = 0;
        for (int j = 0; j < 4; j++) { int s = ws[j]; ws[j] = run; run += s; }
    }
    __syncthreads();
    if (t < NB) part[t] = x - v + ws[w];
}

__global__ __launch_bounds__(1024) void scan_add(
    const int* __restrict__ part, int* __restrict__ rowptr, int* __restrict__ cursor)
{
    const int i = blockIdx.x * 1024 + threadIdx.x;
    if (i < NN) {
        int r = rowptr[i] + part[blockIdx.x];
        rowptr[i] = r;
        cursor[i] = r;
    }
    if (i == 0) rowptr[NN] = EE;
}

__global__ void scatter_csr(const int* __restrict__ src, const int* __restrict__ dst,
                            int* __restrict__ cursor, int* __restrict__ srcs)
{
    int e = blockIdx.x * blockDim.x + threadIdx.x;
    if (e >= EE) return;
    int d = __ldg(dst + e);
    int pos = atomicAdd(cursor + d, 1);
    srcs[pos] = __ldg(src + e);
}

// ---------------------------------------------------------------------------
// atomic-free mean aggregation from fp16 table: one warp per node.
// Lane owns 4 features (one uint2 = 4 halves); accumulate fp32; write fp32.
// Per-edge traffic: 256 B (vs 512 B for fp32) -> half the LTS load.
// ---------------------------------------------------------------------------
__global__ __launch_bounds__(256) void aggregate_h(
    const __half* __restrict__ feat16,
    const int*    __restrict__ rowptr,
    const int*    __restrict__ srcs,
    float*        __restrict__ agg)
{
    const int node = blockIdx.x * 8 + (threadIdx.x >> 5);
    const int lane = threadIdx.x & 31;
    if (node >= NN) return;

    const int beg = __ldg(rowptr + node);
    const int end = __ldg(rowptr + node + 1);

    const uint2* fb = (const uint2*)feat16 + lane;   // row = 32 uint2

    float a0 = 0.f, a1 = 0.f, a2 = 0.f, a3 = 0.f;
    int e = beg;
    for (; e + 4 <= end; e += 4) {
        int s0 = __ldg(srcs + e);
        int s1 = __ldg(srcs + e + 1);
        int s2 = __ldg(srcs + e + 2);
        int s3 = __ldg(srcs + e + 3);
        uint2 u0 = __ldg(fb + (size_t)s0 * 32);
        uint2 u1 = __ldg(fb + (size_t)s1 * 32);
        uint2 u2 = __ldg(fb + (size_t)s2 * 32);
        uint2 u3 = __ldg(fb + (size_t)s3 * 32);
#pragma unroll
        for (int j = 0; j < 4; j++) {
            uint2 u = (j == 0) ? u0 : (j == 1) ? u1 : (j == 2) ? u2 : u3;
            float2 f0 = __half22float2(*(__half2*)&u.x);
            float2 f1 = __half22float2(*(__half2*)&u.y);
            a0 += f0.x; a1 += f0.y; a2 += f1.x; a3 += f1.y;
        }
    }
    for (; e < end; e++) {
        int s0 = __ldg(srcs + e);
        uint2 u = __ldg(fb + (size_t)s0 * 32);
        float2 f0 = __half22float2(*(__half2*)&u.x);
        float2 f1 = __half22float2(*(__half2*)&u.y);
        a0 += f0.x; a1 += f0.y; a2 += f1.x; a3 += f1.y;
    }

    const int deg = end - beg;
    const float inv = 1.f / (float)(deg > 1 ? deg : 1);
    float4 o = make_float4(a0 * inv, a1 * inv, a2 * inv, a3 * inv);
    *((float4*)(agg + (size_t)node * C) + lane) = o;
}

// ---------------------------------------------------------------------------
// HMMA fused dual-matmul layer (split-bf16 emulated fp32).
// Optional fp16 mirror of the output (outh) for the next layer's gather.
// ---------------------------------------------------------------------------
#define PITCH  72
#define SLAB_B (128 * PITCH * 2)
#define AH_OFF 0
#define AL_OFF SLAB_B
#define WH_OFF (2 * SLAB_B)
#define WL_OFF (3 * SLAB_B)
#define SMEM_BYTES (4 * SLAB_B)         // 73728

__global__ __launch_bounds__(256, 2) void hmma_layer(
    const float* __restrict__ A1, const float* __restrict__ A2,
    const __nv_bfloat16* __restrict__ whi, const __nv_bfloat16* __restrict__ wlo,
    int s0, int s1,
    const float* __restrict__ bias,
    float* __restrict__ out, __half* __restrict__ outh, int nrows)
{
    extern __shared__ char sm[];
    const uint32_t smb = smem_u32(sm);
    const int t = threadIdx.x, wid = t >> 5, lane = t & 31;
    const int nb = blockIdx.x * 128;

    const int mBase = (wid & 3) * 32;
    const int nBase = (wid >> 2) * 64;

    const int arow = (lane & 7) + ((lane >> 3) & 1) * 8;
    const int acol = (lane >> 4) * 8;
    const int brow = (lane & 7) + (lane >> 4) * 8;
    const int bcol = ((lane >> 3) & 1) * 8;
    const uint32_t aoff0 = ((mBase + arow) * PITCH + acol) * 2;
    const uint32_t aoff1 = aoff0 + 16 * PITCH * 2;
    const uint32_t boff  = ((nBase + brow) * PITCH + bcol) * 2;

    float acc[2][8][4];
#pragma unroll
    for (int mt = 0; mt < 2; mt++)
#pragma unroll
        for (int nt = 0; nt < 8; nt++)
#pragma unroll
            for (int j = 0; j < 4; j++) acc[mt][nt][j] = 0.f;

#pragma unroll 1
    for (int pass = 0; pass < 2; pass++) {
        const float* A = pass ? A2 : A1;
        const __nv_bfloat16* Wh = whi + (size_t)(pass ? s1 : s0) * 16384;
        const __nv_bfloat16* Wl = wlo + (size_t)(pass ? s1 : s0) * 16384;

#pragma unroll 1
        for (int chunk = 0; chunk < 2; chunk++) {
            const int k0 = chunk * 64;

            for (int i = t; i < 2048; i += 256) {
                const int slab = i >> 10;
                const int r    = (i >> 3) & 127;
                const int seg  = i & 7;
                const uint32_t sa = smb + (slab ? WL_OFF : WH_OFF)
                                  + r * (PITCH * 2) + seg * 16;
                const __nv_bfloat16* g = (slab ? Wl : Wh) + (size_t)r * 128 + k0 + seg * 8;
                cp16(sa, g);
            }
            asm volatile("cp.async.commit_group;" ::: "memory");

            for (int i = t; i < 2048; i += 256) {
                const int r  = i >> 4;
                const int f4 = i & 15;
                const int gn = nb + r;
                float4 v = make_float4(0.f, 0.f, 0.f, 0.f);
                if (gn < nrows)
                    v = __ldg((const float4*)(A + (size_t)gn * C + k0 + f4 * 4));
                uint32_t h0 = packbf2(v.x, v.y);
                uint32_t h1 = packbf2(v.z, v.w);
                float l00 = v.x - __uint_as_float(h0 << 16);
                float l01 = v.y - __uint_as_float(h0 & 0xFFFF0000u);
                float l10 = v.z - __uint_as_float(h1 << 16);
                float l11 = v.w - __uint_as_float(h1 & 0xFFFF0000u);
                uint32_t l0 = packbf2(l00, l01);
                uint32_t l1 = packbf2(l10, l11);
                const size_t so = (size_t)r * (PITCH * 2) + f4 * 8;
                *(uint2*)(sm + AH_OFF + so) = make_uint2(h0, h1);
                *(uint2*)(sm + AL_OFF + so) = make_uint2(l0, l1);
            }
            asm volatile("cp.async.wait_group 0;" ::: "memory");
            __syncthreads();

#pragma unroll
            for (int ks = 0; ks < 4; ks++) {
                uint32_t ah0[4], ah1[4], al0[4], al1[4];
                ldsm4(smb + AH_OFF + aoff0 + ks * 32, ah0);
                ldsm4(smb + AH_OFF + aoff1 + ks * 32, ah1);
                ldsm4(smb + AL_OFF + aoff0 + ks * 32, al0);
                ldsm4(smb + AL_OFF + aoff1 + ks * 32, al1);
#pragma unroll
                for (int p = 0; p < 4; p++) {
                    uint32_t bh[4], bl[4];
                    const uint32_t bo = boff + p * (16 * PITCH * 2) + ks * 32;
                    ldsm4(smb + WH_OFF + bo, bh);
                    ldsm4(smb + WL_OFF + bo, bl);
                    mma16816(acc[0][2 * p],     ah0, bh);
                    mma16816(acc[1][2 * p],     ah1, bh);
                    mma16816(acc[0][2 * p],     al0, bh);
                    mma16816(acc[1][2 * p],     al1, bh);
                    mma16816(acc[0][2 * p],     ah0, bl);
                    mma16816(acc[1][2 * p],     ah1, bl);
                    mma16816(acc[0][2 * p + 1], ah0, bh + 2);
                    mma16816(acc[1][2 * p + 1], ah1, bh + 2);
                    mma16816(acc[0][2 * p + 1], al0, bh + 2);
                    mma16816(acc[1][2 * p + 1], al1, bh + 2);
                    mma16816(acc[0][2 * p + 1], ah0, bl + 2);
                    mma16816(acc[1][2 * p + 1], ah1, bl + 2);
                }
            }
            __syncthreads();
        }
    }

    // -- epilogue: bias + relu; fp32 stores (+ optional fp16 mirror) --
    const int qrow = lane >> 2;
    const int qk   = (lane & 3) * 2;
#pragma unroll
    for (int nt = 0; nt < 8; nt++) {
        const int cl = nBase + nt * 8 + qk;
        const float2 b = __ldg((const float2*)(bias + cl));
#pragma unroll
        for (int mt = 0; mt < 2; mt++) {
            const int r0 = nb + mBase + mt * 16 + qrow;
            if (r0 < nrows) {
                float2 o;
                o.x = fmaxf(acc[mt][nt][0] + b.x, 0.f);
                o.y = fmaxf(acc[mt][nt][1] + b.y, 0.f);
                *(float2*)(out + (size_t)r0 * C + cl) = o;
                if (outh) {
                    __half2 hh = __floats2half2_rn(o.x, o.y);
                    *(__half2*)(outh + (size_t)r0 * C + cl) = hh;
                }
            }
            const int r1 = r0 + 8;
            if (r1 < nrows) {
                float2 o;
                o.x = fmaxf(acc[mt][nt][2] + b.x, 0.f);
                o.y = fmaxf(acc[mt][nt][3] + b.y, 0.f);
                *(float2*)(out + (size_t)r1 * C + cl) = o;
                if (outh) {
                    __half2 hh = __floats2half2_rn(o.x, o.y);
                    *(__half2*)(outh + (size_t)r1 * C + cl) = hh;
                }
            }
        }
    }
}

// ---------------------------------------------------------------------------
// launch
// ---------------------------------------------------------------------------
extern "C" void kernel_launch(void* const* d_in, const int* in_sizes, int n_in,
                              void* d_out, int out_size)
{
    const float* x    = (const float*)d_in[0];
    const int*   ei   = (const int*)  d_in[1];
    const float* Wl1  = (const float*)d_in[2];
    const float* Wr1  = (const float*)d_in[3];
    const float* b1   = (const float*)d_in[4];
    const float* Wl2  = (const float*)d_in[5];
    const float* Wr2  = (const float*)d_in[6];
    const float* b2   = (const float*)d_in[7];
    const float* Wlin = (const float*)d_in[8];
    const float* blin = (const float*)d_in[9];
    float*       out  = (float*)d_out;

    const int* src = ei;
    const int* dst = ei + EE;

    void *agg_v, *h1_v, *h2_v, *xh_v, *h1h_v, *cnt_v, *rp_v, *cur_v, *part_v,
         *srcs_v, *whi_v, *wlo_v;
    cudaGetSymbolAddress(&agg_v, g_agg);
    cudaGetSymbolAddress(&h1_v,  g_h1);
    cudaGetSymbolAddress(&h2_v,  g_h2);
    cudaGetSymbolAddress(&xh_v,  g_xh);
    cudaGetSymbolAddress(&h1h_v, g_h1h);
    cudaGetSymbolAddress(&cnt_v, g_cnt);
    cudaGetSymbolAddress(&rp_v,  g_rowptr);
    cudaGetSymbolAddress(&cur_v, g_cursor);
    cudaGetSymbolAddress(&part_v, g_part);
    cudaGetSymbolAddress(&srcs_v, g_srcs);
    cudaGetSymbolAddress(&whi_v, g_whi);
    cudaGetSymbolAddress(&wlo_v, g_wlo);
    float*  agg = (float*)agg_v;
    float*  h1  = (float*)h1_v;
    float*  h2  = (float*)h2_v;
    __half* xh  = (__half*)xh_v;
    __half* h1h = (__half*)h1h_v;
    int*    cnt = (int*)cnt_v;
    int*    rowptr = (int*)rp_v;
    int*    cursor = (int*)cur_v;
    int*    part   = (int*)part_v;
    int*    srcs   = (int*)srcs_v;
    __nv_bfloat16* whi = (__nv_bfloat16*)whi_v;
    __nv_bfloat16* wlo = (__nv_bfloat16*)wlo_v;

    cudaFuncSetAttribute(hmma_layer,
                         cudaFuncAttributeMaxDynamicSharedMemorySize, SMEM_BYTES);

    const int eblk  = (EE + 255) / 256;         // 6250
    const int gblk  = (NN + 127) / 128;         // 782
    const int ablk  = (NN + 7) / 8;             // 12500
    const int wblk  = (6 * 16384 + 255) / 256;
    const int n4    = NN * C / 4;               // 3,200,000
    const int hblk  = (n4 + 255) / 256;

    // ---- prep: weight split + fp16 table of x + CSR build ----
    split_weights<<<wblk, 256>>>(Wl1, Wr1, Wl2, Wr2, Wlin, whi, wlo);
    to_half<<<hblk, 256>>>(x, xh, n4);
    zero_i<<<(NN + 255) / 256, 256>>>(cnt, NN);
    hist_kernel<<<eblk, 256>>>(dst, cnt);
    scan_blk<<<NB, 1024>>>(cnt, rowptr, part);
    scan_part<<<1, 128>>>(part);
    scan_add<<<NB, 1024>>>(part, rowptr, cursor);
    scatter_csr<<<eblk, 256>>>(src, dst, cursor, srcs);

    // ---- conv1: gather16(x) -> agg; h1 = relu(agg·Wl1 + x·Wr1 + b1) (+fp16 mirror) ----
    aggregate_h<<<ablk, 256>>>(xh, rowptr, srcs, agg);
    hmma_layer<<<gblk, 256, SMEM_BYTES>>>(agg, x, whi, wlo, 0, 1, b1, h1, h1h, NN);

    // ---- conv2: gather16(h1) -> agg; h2 = relu(agg·Wl2 + h1·Wr2 + b2) ----
    aggregate_h<<<ablk, 256>>>(h1h, rowptr, srcs, agg);
    hmma_layer<<<gblk, 256, SMEM_BYTES>>>(agg, h1, whi, wlo, 2, 3, b2, h2, nullptr, NN);

    // ---- JK-cat + linear head ----
    hmma_layer<<<gblk, 256, SMEM_BYTES>>>(h1, h2, whi, wlo, 4, 5, blin, out, nullptr, NN);
}